// round 2
// baseline (speedup 1.0000x reference)
#include <cuda_runtime.h>

// Problem shape (fixed by the dataset): moved/label are [B=2, 1, D=160, H=192, W=160] fp32.
#define DIM_B 2
#define DIM_D 160
#define DIM_H 192
#define DIM_W 160

// Tile config
#define TX 32          // outputs per block in x
#define TY 8           // outputs per block in y
#define CZ 32          // z-chunk per block
#define SMX 36         // padded smem row stride (TX+2 = 34, pad to 36)
#define SMY (TY + 2)   // 10
#define NTHREADS 256

__device__ double g_acc;

__global__ void zero_kernel() { g_acc = 0.0; }

__global__ __launch_bounds__(NTHREADS) void sobel_loss_kernel(
    const float* __restrict__ moved, const float* __restrict__ label)
{
    __shared__ float sm[SMY][SMX];
    __shared__ float red[NTHREADS / 32];

    const int tid = threadIdx.x;
    const int tx  = tid & 31;        // 0..31
    const int ty  = tid >> 5;        // 0..7

    const int x0 = blockIdx.x * TX;
    const int y0 = blockIdx.y * TY;
    const int nzc = DIM_D / CZ;
    const int b   = blockIdx.z / nzc;
    const int z0  = (blockIdx.z % nzc) * CZ;

    const size_t vol = (size_t)DIM_D * DIM_H * DIM_W;
    const float* mp = moved + (size_t)b * vol;
    const float* lp = label + (size_t)b * vol;

    // ---- plane loader: sm[sy][sx] = d(z, y0-1+sy, x0-1+sx), zero-padded ----
    #define LOAD_PLANE(ZP)                                                     \
    do {                                                                       \
        const int zz = (ZP);                                                   \
        const bool zin = (zz >= 0) && (zz < DIM_D);                            \
        for (int i = tid; i < SMY * 34; i += NTHREADS) {                       \
            const int sy = i / 34;                                             \
            const int sx = i - sy * 34;                                        \
            const int gx = x0 - 1 + sx;                                        \
            const int gy = y0 - 1 + sy;                                        \
            float v = 0.0f;                                                    \
            if (zin && gx >= 0 && gx < DIM_W && gy >= 0 && gy < DIM_H) {       \
                const size_t idx = ((size_t)zz * DIM_H + gy) * DIM_W + gx;     \
                v = mp[idx] - lp[idx];                                         \
            }                                                                  \
            sm[sy][sx] = v;                                                    \
        }                                                                      \
    } while (0)

    // ---- per-plane separable partials for this thread's (x,y) column ----
    // X = Sy(Dx d), Y = Dy(Sx d), S = Sy(Sx d)
    #define COMPUTE_XYS(X_, Y_, S_)                                            \
    do {                                                                       \
        float v0, v1, v2, rs0, rs1, rs2, rd0, rd2;                             \
        v0 = sm[ty + 0][tx]; v1 = sm[ty + 0][tx + 1]; v2 = sm[ty + 0][tx + 2]; \
        rs0 = v0 + 2.0f * v1 + v2; rd0 = v2 - v0;                              \
        v0 = sm[ty + 1][tx]; v1 = sm[ty + 1][tx + 1]; v2 = sm[ty + 1][tx + 2]; \
        rs1 = v0 + 2.0f * v1 + v2; float rd1 = v2 - v0;                        \
        v0 = sm[ty + 2][tx]; v1 = sm[ty + 2][tx + 1]; v2 = sm[ty + 2][tx + 2]; \
        rs2 = v0 + 2.0f * v1 + v2; rd2 = v2 - v0;                              \
        X_ = rd0 + 2.0f * rd1 + rd2;                                           \
        S_ = rs0 + 2.0f * rs1 + rs2;                                           \
        Y_ = rs2 - rs0;                                                        \
    } while (0)

    float Xp, Yp, Sp, Xc, Yc, Sc;

    LOAD_PLANE(z0 - 1);
    __syncthreads();
    COMPUTE_XYS(Xp, Yp, Sp);
    __syncthreads();

    LOAD_PLANE(z0);
    __syncthreads();
    COMPUTE_XYS(Xc, Yc, Sc);
    __syncthreads();

    float acc = 0.0f;

    #pragma unroll 4
    for (int z = z0; z < z0 + CZ; ++z) {
        LOAD_PLANE(z + 1);
        __syncthreads();
        float Xn, Yn, Sn;
        COMPUTE_XYS(Xn, Yn, Sn);

        const float gx = Xp + 2.0f * Xc + Xn;   // Sz applied over z
        const float gy = Yp + 2.0f * Yc + Yn;
        const float gz = Sn - Sp;               // Dz (sign irrelevant under abs)
        acc += fabsf(gx) + fabsf(gy) + fabsf(gz);

        Xp = Xc; Yp = Yc; Sp = Sc;
        Xc = Xn; Yc = Yn; Sc = Sn;
        __syncthreads();
    }

    // ---- block reduction ----
    #pragma unroll
    for (int o = 16; o > 0; o >>= 1)
        acc += __shfl_down_sync(0xffffffffu, acc, o);
    if (tx == 0) red[ty] = acc;
    __syncthreads();
    if (tid == 0) {
        float s = 0.0f;
        #pragma unroll
        for (int i = 0; i < NTHREADS / 32; ++i) s += red[i];
        atomicAdd(&g_acc, (double)s);
    }

    #undef LOAD_PLANE
    #undef COMPUTE_XYS
}

__global__ void finalize_kernel(float* __restrict__ out)
{
    // divisor = 3 * B * D * H * W = 3 * 9,830,400
    out[0] = (float)(g_acc / (3.0 * (double)DIM_B * DIM_D * DIM_H * DIM_W));
}

extern "C" void kernel_launch(void* const* d_in, const int* in_sizes, int n_in,
                              void* d_out, int out_size)
{
    (void)in_sizes; (void)n_in; (void)out_size;
    const float* moved = (const float*)d_in[0];
    const float* label = (const float*)d_in[1];
    float* out = (float*)d_out;

    zero_kernel<<<1, 1>>>();

    dim3 grid(DIM_W / TX, DIM_H / TY, DIM_B * (DIM_D / CZ));  // (5, 24, 10) = 1200 blocks
    sobel_loss_kernel<<<grid, NTHREADS>>>(moved, label);

    finalize_kernel<<<1, 1>>>(out);
}

// round 5
// speedup vs baseline: 1.2810x; 1.2810x over previous
#include <cuda_runtime.h>

// Shape fixed by dataset: [B=2, 1, D=160, H=192, W=160] fp32.
#define DW 160
#define DH 192
#define DD 160
#define DB 2

#define CZ   16                   // z-planes per block
#define NCHUNK (DD / CZ)          // 10
#define TY   8                    // output rows per block
#define VX   4                    // outputs per thread in x
#define TXN  40                   // thread columns (40*4 = 160 = full W)
#define NT   320                  // threads per block
#define SMS  168                  // smem row stride in floats (pad3|halo|160|halo|pad3)
#define SMROWS 10                 // TY + 2
#define NITEMS 400                // float4 load slots per plane (10 rows * 40)
#define NBLOCKS ((DH / TY) * DB * NCHUNK)   // 24*2*10 = 480

__device__ double        g_acc = 0.0;
__device__ unsigned int  g_cnt = 0;

__global__ __launch_bounds__(NT, 2) void sobel_loss_kernel(
    const float* __restrict__ moved, const float* __restrict__ label,
    float* __restrict__ out)
{
    __shared__ __align__(16) float sm[2][SMROWS * SMS];
    __shared__ float red[NT / 32];

    const int tid = threadIdx.x;
    const int txi = tid % TXN;            // 0..39
    const int tyi = tid / TXN;            // 0..7

    const int y0 = blockIdx.y * TY;
    const int b  = blockIdx.z / NCHUNK;
    const int z0 = (blockIdx.z % NCHUNK) * CZ;

    const size_t vol = (size_t)DD * DH * DW;
    const float* mp = moved + (size_t)b * vol;
    const float* lp = label + (size_t)b * vol;

    // ---- per-thread plane-load slots (addresses constant across planes) ----
    // slot 0: item k = tid (always < 400)
    const int  r0   = tyi;                       // rows 0..7
    const int  gy0  = y0 - 1 + r0;
    const bool yv0  = (gy0 >= 0) && (gy0 < DH);
    const int  goff0 = gy0 * DW + 4 * txi;       // used only when yv0
    const int  soff0 = r0 * SMS + 4 + 4 * txi;
    // slot 1: item k = tid + 320 (valid when tid < 80) -> rows 8,9
    const bool kv1  = tid < (NITEMS - NT);
    const int  k1   = tid + NT;
    const int  r1   = k1 / TXN;
    const int  c1   = k1 % TXN;
    const int  gy1  = y0 - 1 + r1;
    const bool yv1  = kv1 && (gy1 >= 0) && (gy1 < DH);
    const int  goff1 = gy1 * DW + 4 * c1;
    const int  soff1 = r1 * SMS + 4 + 4 * c1;

    // zero the x-halo columns (index 3 and 4+W=164) of both buffers, once
    if (tid < 40) {
        int bb = tid / 20;
        int rr = (tid % 20) >> 1;
        int cc = (tid & 1) ? (4 + DW) : 3;
        sm[bb][rr * SMS + cc] = 0.0f;
    }

    float4 v0, v1;   // prefetch registers (moved - label)

    auto gload = [&](int z) {
        v0 = make_float4(0.f, 0.f, 0.f, 0.f);
        v1 = v0;
        if (z >= 0 && z < DD) {
            const size_t zb = (size_t)z * (DH * DW);
            if (yv0) {
                float4 m = *(const float4*)(mp + zb + goff0);
                float4 l = *(const float4*)(lp + zb + goff0);
                v0 = make_float4(m.x - l.x, m.y - l.y, m.z - l.z, m.w - l.w);
            }
            if (yv1) {
                float4 m = *(const float4*)(mp + zb + goff1);
                float4 l = *(const float4*)(lp + zb + goff1);
                v1 = make_float4(m.x - l.x, m.y - l.y, m.z - l.z, m.w - l.w);
            }
        }
    };

    auto sts = [&](int p) {
        *(float4*)(&sm[p][soff0]) = v0;
        if (kv1) *(float4*)(&sm[p][soff1]) = v1;
    };

    // per-plane separable partials for this thread's 4 outputs:
    // X = Sy(Dx d), Y = Dy(Sx d), S = Sy(Sx d)
    auto compute = [&](int p, float X[VX], float Y[VX], float S[VX]) {
        float s_[3][VX], d_[3][VX];
        #pragma unroll
        for (int rr = 0; rr < 3; ++rr) {
            const float* rowp = &sm[p][(tyi + rr) * SMS + 4 * txi];
            float a0 = rowp[3];                      // gx-1 of first output
            float4 m = *(const float4*)(rowp + 4);   // gx..gx+3
            float a5 = rowp[8];                      // gx+4
            float v[6] = {a0, m.x, m.y, m.z, m.w, a5};
            #pragma unroll
            for (int j = 0; j < VX; ++j) {
                s_[rr][j] = v[j] + 2.0f * v[j + 1] + v[j + 2];
                d_[rr][j] = v[j + 2] - v[j];
            }
        }
        #pragma unroll
        for (int j = 0; j < VX; ++j) {
            X[j] = d_[0][j] + 2.0f * d_[1][j] + d_[2][j];
            S[j] = s_[0][j] + 2.0f * s_[1][j] + s_[2][j];
            Y[j] = s_[2][j] - s_[0][j];
        }
    };

    float Xp[VX], Yp[VX], Sp[VX], Xc[VX], Yc[VX], Sc[VX], Xn[VX], Yn[VX], Sn[VX];

    // ---- software-pipelined prologue ----
    gload(z0 - 1);
    sts(0);
    gload(z0);                 // prefetch next plane while buffer 0 settles
    __syncthreads();
    compute(0, Xp, Yp, Sp);
    sts(1);                    // writes buf1; everyone read buf0 before own sts
    gload(z0 + 1);
    __syncthreads();
    compute(1, Xc, Yc, Sc);

    float acc = 0.0f;
    int p = 0;

    #pragma unroll 3
    for (int i = 0; i < CZ; ++i) {
        sts(p);                            // plane z0+i+1 -> buf p
        if (i < CZ - 1) gload(z0 + i + 2); // prefetch plane z0+i+2
        __syncthreads();
        compute(p, Xn, Yn, Sn);

        #pragma unroll
        for (int j = 0; j < VX; ++j) {
            float gx = Xp[j] + 2.0f * Xc[j] + Xn[j];  // Sz over z
            float gy = Yp[j] + 2.0f * Yc[j] + Yn[j];
            float gz = Sn[j] - Sp[j];                 // Dz (sign dies under abs)
            acc += fabsf(gx) + fabsf(gy) + fabsf(gz);
        }
        #pragma unroll
        for (int j = 0; j < VX; ++j) {
            Xp[j] = Xc[j]; Yp[j] = Yc[j]; Sp[j] = Sc[j];
            Xc[j] = Xn[j]; Yc[j] = Yn[j]; Sc[j] = Sn[j];
        }
        p ^= 1;
    }

    // ---- reduction: warp shuffle -> smem -> block sum -> global atomic ----
    #pragma unroll
    for (int o = 16; o > 0; o >>= 1)
        acc += __shfl_down_sync(0xffffffffu, acc, o);
    if ((tid & 31) == 0) red[tid >> 5] = acc;
    __syncthreads();

    if (tid == 0) {
        float s = 0.0f;
        #pragma unroll
        for (int i = 0; i < NT / 32; ++i) s += red[i];
        atomicAdd(&g_acc, (double)s);
        __threadfence();
        unsigned old = atomicInc(&g_cnt, NBLOCKS - 1);  // wraps to 0 at NBLOCKS-1
        if (old == NBLOCKS - 1) {
            // last block: all adds are visible; write result, reset for replay
            double total = atomicAdd(&g_acc, 0.0);
            out[0] = (float)(total / (3.0 * (double)DB * DD * DH * DW));
            g_acc = 0.0;
            __threadfence();
        }
    }
}

extern "C" void kernel_launch(void* const* d_in, const int* in_sizes, int n_in,
                              void* d_out, int out_size)
{
    (void)in_sizes; (void)n_in; (void)out_size;
    const float* moved = (const float*)d_in[0];
    const float* label = (const float*)d_in[1];
    float* out = (float*)d_out;

    dim3 grid(1, DH / TY, DB * NCHUNK);   // (1, 24, 20) = 480 blocks
    sobel_loss_kernel<<<grid, NT>>>(moved, label, out);
}